// round 5
// baseline (speedup 1.0000x reference)
#include <cuda_runtime.h>
#include <math.h>

#define CC 64
#define KK 16
#define NN 8192
#define BB 8

// Shared memory layout (in floats)
#define OFF_A1    0        // 64x4 folded cf_w1
#define OFF_a1    256      // 64
#define OFF_A2    320      // 64x2 folded pl_w1
#define OFF_a2    448      // 64
#define OFF_W1    512      // cf_w2 64x64
#define OFF_b1v   4608     // cf_b2
#define OFF_W2    4672     // pl_w2 64x64
#define OFF_b2v   8768     // pl_b2
#define OFF_M2    8832     // folded ge_w1 64x64
#define OFF_b3    12928    // folded ge bias
#define OFF_W3    12992    // ge_w2 64x64
#define OFF_bo    17088    // ge_b2
#define OFF_D     17152    // d 64x16
#define SMEM_FLOATS 18176
#define SMEM_BYTES  (SMEM_FLOATS * 4)

__global__ __launch_bounds__(256)
void geo_enc_kernel(
    const float* __restrict__ nb,   const float* __restrict__ cx,   const float* __restrict__ dmat,
    const float* __restrict__ cf_w1, const float* __restrict__ cf_b1, const float* __restrict__ cf_g,
    const float* __restrict__ cf_be, const float* __restrict__ cf_m,  const float* __restrict__ cf_v,
    const float* __restrict__ cf_w2, const float* __restrict__ cf_b2,
    const float* __restrict__ pl_w1, const float* __restrict__ pl_b1, const float* __restrict__ pl_g,
    const float* __restrict__ pl_be, const float* __restrict__ pl_m,  const float* __restrict__ pl_v,
    const float* __restrict__ pl_w2, const float* __restrict__ pl_b2,
    const float* __restrict__ ge_w1, const float* __restrict__ ge_b1, const float* __restrict__ ge_g,
    const float* __restrict__ ge_be, const float* __restrict__ ge_m,  const float* __restrict__ ge_v,
    const float* __restrict__ ge_w2, const float* __restrict__ ge_b2,
    float* __restrict__ out)
{
    extern __shared__ float sm[];
    const int tid = threadIdx.x;

    // ---- Prologue: load + BN-fold weights into shared memory ----
    for (int i = tid; i < 4096; i += 256) {
        sm[OFF_W1 + i] = cf_w2[i];
        sm[OFF_W2 + i] = pl_w2[i];
        sm[OFF_W3 + i] = ge_w2[i];
    }
    for (int i = tid; i < 1024; i += 256) sm[OFF_D + i] = dmat[i];
    if (tid < 64) {
        const int c = tid;
        float s = cf_g[c] * rsqrtf(cf_v[c] + 1e-5f);
        sm[OFF_A1 + c*4 + 0] = s * cf_w1[c*4 + 0];
        sm[OFF_A1 + c*4 + 1] = s * cf_w1[c*4 + 1];
        sm[OFF_A1 + c*4 + 2] = s * cf_w1[c*4 + 2];
        sm[OFF_A1 + c*4 + 3] = s * cf_w1[c*4 + 3];
        sm[OFF_a1 + c] = s * (cf_b1[c] - cf_m[c]) + cf_be[c];

        s = pl_g[c] * rsqrtf(pl_v[c] + 1e-5f);
        sm[OFF_A2 + c*2 + 0] = s * pl_w1[c*2 + 0];
        sm[OFF_A2 + c*2 + 1] = s * pl_w1[c*2 + 1];
        sm[OFF_a2 + c] = s * (pl_b1[c] - pl_m[c]) + pl_be[c];

        s = ge_g[c] * rsqrtf(ge_v[c] + 1e-5f);
        for (int j = 0; j < 64; j++) sm[OFF_M2 + c*64 + j] = s * ge_w1[c*64 + j];
        sm[OFF_b3 + c] = s * (ge_b1[c] - ge_m[c]) + ge_be[c];

        sm[OFF_b1v + c] = cf_b2[c];
        sm[OFF_b2v + c] = pl_b2[c];
        sm[OFF_bo  + c] = ge_b2[c];
    }
    __syncthreads();

    // ---- Position mapping: one thread per (b, n, k) ----
    const int k  = tid & 15;
    const int nl = tid >> 4;          // 0..15
    const int tile = blockIdx.x;      // 0..4095
    const int b  = tile >> 9;         // 512 tiles per batch
    const int nt = tile & 511;
    const int n  = nt * 16 + nl;

    const float* nbb = nb + (size_t)b * 3 * NN * KK;
    const float* cxb = cx + (size_t)b * 3 * NN;
    const float dx = nbb[(0 * NN + n) * KK + k] - cxb[0 * NN + n];
    const float dy = nbb[(1 * NN + n) * KK + k] - cxb[1 * NN + n];
    const float dz = nbb[(2 * NN + n) * KK + k] - cxb[2 * NN + n];

    const float r   = sqrtf(dx*dx + dy*dy + dz*dz);
    const float rxy = sqrtf(dx*dx + dy*dy);
    const float ce  = (r   > 0.f) ? (rxy / r)  : 0.f;   // cos_theta_e (0/0 -> 0)
    const float ca  = (rxy > 0.f) ? (dy / rxy) : 0.f;   // cos_theta_a (0/0 -> 0)

    float h[64];
    float z[64];

    // Stage 1: h1 = relu(A1 @ [dx,dy,dz,r] + a1)
#pragma unroll
    for (int c = 0; c < 64; c++) {
        const float4 w = *(const float4*)(sm + OFF_A1 + c*4);
        float v = fmaf(w.x, dx, fmaf(w.y, dy, fmaf(w.z, dz, fmaf(w.w, r, sm[OFF_a1 + c]))));
        h[c] = fmaxf(v, 0.f);
    }

    // Stage 2: z = cf_w2 @ h1 + cf_b2   (enc)
#pragma unroll
    for (int c = 0; c < 64; c++) {
        const float4* row = (const float4*)(sm + OFF_W1 + c*64);
        float s0 = sm[OFF_b1v + c], s1 = 0.f, s2 = 0.f, s3 = 0.f;
#pragma unroll
        for (int j = 0; j < 16; j++) {
            const float4 w = row[j];
            s0 = fmaf(w.x, h[4*j + 0], s0);
            s1 = fmaf(w.y, h[4*j + 1], s1);
            s2 = fmaf(w.z, h[4*j + 2], s2);
            s3 = fmaf(w.w, h[4*j + 3], s3);
        }
        z[c] = (s0 + s1) + (s2 + s3);
    }

    // Stage 3: h2 = relu(A2 @ [ca, ce] + a2)
#pragma unroll
    for (int c = 0; c < 64; c++) {
        const float2 w = *(const float2*)(sm + OFF_A2 + c*2);
        float v = fmaf(w.x, ca, fmaf(w.y, ce, sm[OFF_a2 + c]));
        h[c] = fmaxf(v, 0.f);
    }

    // Stage 4: z += d[c][k] * (pl_w2 @ h2 + pl_b2)
#pragma unroll
    for (int c = 0; c < 64; c++) {
        const float4* row = (const float4*)(sm + OFF_W2 + c*64);
        float s0 = sm[OFF_b2v + c], s1 = 0.f, s2 = 0.f, s3 = 0.f;
#pragma unroll
        for (int j = 0; j < 16; j++) {
            const float4 w = row[j];
            s0 = fmaf(w.x, h[4*j + 0], s0);
            s1 = fmaf(w.y, h[4*j + 1], s1);
            s2 = fmaf(w.z, h[4*j + 2], s2);
            s3 = fmaf(w.w, h[4*j + 3], s3);
        }
        z[c] = fmaf(sm[OFF_D + c*16 + k], (s0 + s1) + (s2 + s3), z[c]);
    }

    // Stage 5: h3 = relu(M2 @ z + b3)   (ge first conv + folded BN)
#pragma unroll
    for (int c = 0; c < 64; c++) {
        const float4* row = (const float4*)(sm + OFF_M2 + c*64);
        float s0 = sm[OFF_b3 + c], s1 = 0.f, s2 = 0.f, s3 = 0.f;
#pragma unroll
        for (int j = 0; j < 16; j++) {
            const float4 w = row[j];
            s0 = fmaf(w.x, z[4*j + 0], s0);
            s1 = fmaf(w.y, z[4*j + 1], s1);
            s2 = fmaf(w.z, z[4*j + 2], s2);
            s3 = fmaf(w.w, z[4*j + 3], s3);
        }
        h[c] = fmaxf((s0 + s1) + (s2 + s3), 0.f);
    }

    // Stage 6: out[c] = ge_w2 @ h3 + ge_b2, coalesced stores
    const size_t base = ((size_t)(b * 64) * NN + n) * KK + k;
#pragma unroll
    for (int c = 0; c < 64; c++) {
        const float4* row = (const float4*)(sm + OFF_W3 + c*64);
        float s0 = sm[OFF_bo + c], s1 = 0.f, s2 = 0.f, s3 = 0.f;
#pragma unroll
        for (int j = 0; j < 16; j++) {
            const float4 w = row[j];
            s0 = fmaf(w.x, h[4*j + 0], s0);
            s1 = fmaf(w.y, h[4*j + 1], s1);
            s2 = fmaf(w.z, h[4*j + 2], s2);
            s3 = fmaf(w.w, h[4*j + 3], s3);
        }
        out[base + (size_t)c * (NN * KK)] = (s0 + s1) + (s2 + s3);
    }
}

extern "C" void kernel_launch(void* const* d_in, const int* in_sizes, int n_in,
                              void* d_out, int out_size) {
    (void)in_sizes; (void)n_in; (void)out_size;

    cudaFuncSetAttribute(geo_enc_kernel,
                         cudaFuncAttributeMaxDynamicSharedMemorySize, SMEM_BYTES);

    const float* nb    = (const float*)d_in[0];
    const float* cx    = (const float*)d_in[1];
    const float* dmat  = (const float*)d_in[2];
    const float* cf_w1 = (const float*)d_in[3];
    const float* cf_b1 = (const float*)d_in[4];
    const float* cf_g  = (const float*)d_in[5];
    const float* cf_be = (const float*)d_in[6];
    const float* cf_m  = (const float*)d_in[7];
    const float* cf_v  = (const float*)d_in[8];
    const float* cf_w2 = (const float*)d_in[9];
    const float* cf_b2 = (const float*)d_in[10];
    const float* pl_w1 = (const float*)d_in[11];
    const float* pl_b1 = (const float*)d_in[12];
    const float* pl_g  = (const float*)d_in[13];
    const float* pl_be = (const float*)d_in[14];
    const float* pl_m  = (const float*)d_in[15];
    const float* pl_v  = (const float*)d_in[16];
    const float* pl_w2 = (const float*)d_in[17];
    const float* pl_b2 = (const float*)d_in[18];
    const float* ge_w1 = (const float*)d_in[19];
    const float* ge_b1 = (const float*)d_in[20];
    const float* ge_g  = (const float*)d_in[21];
    const float* ge_be = (const float*)d_in[22];
    const float* ge_m  = (const float*)d_in[23];
    const float* ge_v  = (const float*)d_in[24];
    const float* ge_w2 = (const float*)d_in[25];
    const float* ge_b2 = (const float*)d_in[26];

    dim3 grid(BB * (NN / 16));   // 4096 tiles of 16 n-positions x 16 k
    dim3 block(256);
    geo_enc_kernel<<<grid, block, SMEM_BYTES>>>(
        nb, cx, dmat,
        cf_w1, cf_b1, cf_g, cf_be, cf_m, cf_v, cf_w2, cf_b2,
        pl_w1, pl_b1, pl_g, pl_be, pl_m, pl_v, pl_w2, pl_b2,
        ge_w1, ge_b1, ge_g, ge_be, ge_m, ge_v, ge_w2, ge_b2,
        (float*)d_out);
}

// round 9
// speedup vs baseline: 14.2858x; 14.2858x over previous
#include <cuda_runtime.h>
#include <cuda_fp16.h>
#include <math.h>
#include <stdint.h>

#define TPB   128
#define GRID  444            // 148 SMs * 3 CTAs
#define NNK   131072         // N*K per (b,c) plane
#define NWT   32768          // total warp tiles (1,048,576 pos / 32)
#define WPITCH 72            // halfs per weight row (conflict-free B-frag loads)
#define DPITCH 68            // floats per ddt row

// ---- smem layout (bytes) ----
#define OFF_W1   0
#define OFF_W2   9216
#define OFF_W3   18432
#define OFF_W4   27648
#define OFF_A1F  36864       // folded cf_w1 [64][4] f32
#define OFF_a1   37888
#define OFF_A2F  38144       // folded pl_w1 [64][2] f32
#define OFF_a2   38656
#define OFF_b1v  38912
#define OFF_b2v  39168
#define OFF_b3v  39424
#define OFF_bov  39680
#define OFF_DDT  39936       // d transposed [16][DPITCH] f32
#define SMEM_BYTES (OFF_DDT + 16*DPITCH*4)   // 44288

__device__ __forceinline__ void mma16816(float* c, const uint32_t* a,
                                         uint32_t b0, uint32_t b1) {
    asm volatile(
        "mma.sync.aligned.m16n8k16.row.col.f32.f16.f16.f32 "
        "{%0,%1,%2,%3}, {%4,%5,%6,%7}, {%8,%9}, {%0,%1,%2,%3};"
        : "+f"(c[0]), "+f"(c[1]), "+f"(c[2]), "+f"(c[3])
        : "r"(a[0]), "r"(a[1]), "r"(a[2]), "r"(a[3]), "r"(b0), "r"(b1));
}
__device__ __forceinline__ uint32_t pack2(float a, float b) {
    __half2 h = __floats2half2_rn(a, b);
    return *reinterpret_cast<uint32_t*>(&h);
}

__global__ void __launch_bounds__(TPB, 3) geo_hmma_kernel(
    const float* __restrict__ nb,    const float* __restrict__ cx,    const float* __restrict__ dmat,
    const float* __restrict__ cf_w1, const float* __restrict__ cf_b1, const float* __restrict__ cf_g,
    const float* __restrict__ cf_be, const float* __restrict__ cf_m,  const float* __restrict__ cf_v,
    const float* __restrict__ cf_w2, const float* __restrict__ cf_b2,
    const float* __restrict__ pl_w1, const float* __restrict__ pl_b1, const float* __restrict__ pl_g,
    const float* __restrict__ pl_be, const float* __restrict__ pl_m,  const float* __restrict__ pl_v,
    const float* __restrict__ pl_w2, const float* __restrict__ pl_b2,
    const float* __restrict__ ge_w1, const float* __restrict__ ge_b1, const float* __restrict__ ge_g,
    const float* __restrict__ ge_be, const float* __restrict__ ge_m,  const float* __restrict__ ge_v,
    const float* __restrict__ ge_w2, const float* __restrict__ ge_b2,
    float* __restrict__ out)
{
    extern __shared__ char smc[];
    __half* W1s = (__half*)(smc + OFF_W1);
    __half* W2s = (__half*)(smc + OFF_W2);
    __half* W3s = (__half*)(smc + OFF_W3);
    __half* W4s = (__half*)(smc + OFF_W4);
    float*  A1F = (float*)(smc + OFF_A1F);
    float*  a1v = (float*)(smc + OFF_a1);
    float*  A2F = (float*)(smc + OFF_A2F);
    float*  a2v = (float*)(smc + OFF_a2);
    float*  b1v = (float*)(smc + OFF_b1v);
    float*  b2v = (float*)(smc + OFF_b2v);
    float*  b3v = (float*)(smc + OFF_b3v);
    float*  bov = (float*)(smc + OFF_bov);
    float*  DDT = (float*)(smc + OFF_DDT);

    const int tid = threadIdx.x;

    // ---- prologue: fold BN, convert weights to f16, pad pitches ----
    for (int idx = tid; idx < 4096; idx += TPB) {
        int n_ = idx >> 6, k_ = idx & 63;
        float s3 = ge_g[n_] * rsqrtf(ge_v[n_] + 1e-5f);
        W1s[n_*WPITCH + k_] = __float2half_rn(cf_w2[idx]);
        W2s[n_*WPITCH + k_] = __float2half_rn(pl_w2[idx]);
        W3s[n_*WPITCH + k_] = __float2half_rn(s3 * ge_w1[idx]);
        W4s[n_*WPITCH + k_] = __float2half_rn(ge_w2[idx]);
    }
    for (int idx = tid; idx < 1024; idx += TPB) {
        int c_ = idx >> 4, k_ = idx & 15;
        DDT[k_*DPITCH + c_] = dmat[idx];
    }
    if (tid < 64) {
        const int c = tid;
        float s = cf_g[c] * rsqrtf(cf_v[c] + 1e-5f);
        A1F[c*4+0] = s * cf_w1[c*4+0];  A1F[c*4+1] = s * cf_w1[c*4+1];
        A1F[c*4+2] = s * cf_w1[c*4+2];  A1F[c*4+3] = s * cf_w1[c*4+3];
        a1v[c] = s * (cf_b1[c] - cf_m[c]) + cf_be[c];

        s = pl_g[c] * rsqrtf(pl_v[c] + 1e-5f);
        A2F[c*2+0] = s * pl_w1[c*2+0];  A2F[c*2+1] = s * pl_w1[c*2+1];
        a2v[c] = s * (pl_b1[c] - pl_m[c]) + pl_be[c];

        s = ge_g[c] * rsqrtf(ge_v[c] + 1e-5f);
        b3v[c] = s * (ge_b1[c] - ge_m[c]) + ge_be[c];
        b1v[c] = cf_b2[c];
        b2v[c] = pl_b2[c];
        bov[c] = ge_b2[c];
    }
    __syncthreads();

    const int lane = tid & 31;
    const int g    = lane >> 2;        // 0..7
    const int T    = lane & 3;         // 0..3
    const int warp_global = blockIdx.x * (TPB/32) + (tid >> 5);
    const int stride = GRID * (TPB/32);

    for (int wt = warp_global; wt < NWT; wt += stride) {
        const int b    = wt >> 12;               // 4096 tiles per batch
        const int pgb0 = (wt & 4095) << 5;       // base position in batch
        const int pgb  = pgb0 + lane;
        const int n    = pgb >> 4;

        // ---- geometry for own position (lane) ----
        const float* nbb = nb + (size_t)b * 3 * NNK;
        const float* cxb = cx + (size_t)b * 3 * 8192;
        const float dx = nbb[0*NNK + pgb] - cxb[0*8192 + n];
        const float dy = nbb[1*NNK + pgb] - cxb[1*8192 + n];
        const float dz = nbb[2*NNK + pgb] - cxb[2*8192 + n];
        const float r   = sqrtf(dx*dx + dy*dy + dz*dz);
        const float rxy = sqrtf(dx*dx + dy*dy);
        const float ce  = (r   > 0.f) ? (rxy / r)  : 0.f;
        const float ca  = (rxy > 0.f) ? (dy / rxy) : 0.f;

        // ---- gather scalars for the 4 rows this lane owns in frag layout ----
        float vdx[4], vdy[4], vdz[4], vr[4], vca[4], vce[4];
#pragma unroll
        for (int rr = 0; rr < 4; ++rr) {
            int src = g + 8*rr;        // rows g, g+8, g+16, g+24
            vdx[rr] = __shfl_sync(0xffffffffu, dx, src);
            vdy[rr] = __shfl_sync(0xffffffffu, dy, src);
            vdz[rr] = __shfl_sync(0xffffffffu, dz, src);
            vr [rr] = __shfl_sync(0xffffffffu, r,  src);
            vca[rr] = __shfl_sync(0xffffffffu, ca, src);
            vce[rr] = __shfl_sync(0xffffffffu, ce, src);
        }

        // ---- stage 1 & 3: build A fragments directly (f16) ----
        uint32_t fa[2][4][4];   // h1 frags  [m][ktile][reg]
        uint32_t fb[2][4][4];   // h2 frags
#pragma unroll
        for (int t = 0; t < 4; ++t) {
#pragma unroll
            for (int half = 0; half < 2; ++half) {
                const int c0 = 16*t + 8*half + 2*T;
                const float4 w10 = *(const float4*)(A1F + c0*4);
                const float4 w11 = *(const float4*)(A1F + (c0+1)*4);
                const float  o10 = a1v[c0], o11 = a1v[c0+1];
                const float2 w20 = *(const float2*)(A2F + c0*2);
                const float2 w21 = *(const float2*)(A2F + (c0+1)*2);
                const float  o20 = a2v[c0], o21 = a2v[c0+1];
#pragma unroll
                for (int rr = 0; rr < 4; ++rr) {
                    float h0 = fmaxf(fmaf(w10.x, vdx[rr], fmaf(w10.y, vdy[rr],
                                     fmaf(w10.z, vdz[rr], fmaf(w10.w, vr[rr], o10)))), 0.f);
                    float h1 = fmaxf(fmaf(w11.x, vdx[rr], fmaf(w11.y, vdy[rr],
                                     fmaf(w11.z, vdz[rr], fmaf(w11.w, vr[rr], o11)))), 0.f);
                    fa[rr>>1][t][2*half + (rr&1)] = pack2(h0, h1);
                    float p0 = fmaxf(fmaf(w20.x, vca[rr], fmaf(w20.y, vce[rr], o20)), 0.f);
                    float p1 = fmaxf(fmaf(w21.x, vca[rr], fmaf(w21.y, vce[rr], o21)), 0.f);
                    fb[rr>>1][t][2*half + (rr&1)] = pack2(p0, p1);
                }
            }
        }

        // ---- GEMM1 (h1 @ cf_w2^T) + GEMM2 (h2 @ pl_w2^T) + z epilogue ----
        uint32_t fz[2][4][4];   // z frags
#pragma unroll
        for (int j = 0; j < 8; ++j) {
            const __half* wr1 = W1s + (8*j + g)*WPITCH + 2*T;
            const __half* wr2 = W2s + (8*j + g)*WPITCH + 2*T;
            uint32_t b1f[4][2], b2f[4][2];
#pragma unroll
            for (int t = 0; t < 4; ++t) {
                b1f[t][0] = *(const uint32_t*)(wr1 + 16*t);
                b1f[t][1] = *(const uint32_t*)(wr1 + 16*t + 8);
                b2f[t][0] = *(const uint32_t*)(wr2 + 16*t);
                b2f[t][1] = *(const uint32_t*)(wr2 + 16*t + 8);
            }
            float c1[2][4] = {{0,0,0,0},{0,0,0,0}};
            float c2[2][4] = {{0,0,0,0},{0,0,0,0}};
#pragma unroll
            for (int t = 0; t < 4; ++t) {
                mma16816(c1[0], fa[0][t], b1f[t][0], b1f[t][1]);
                mma16816(c1[1], fa[1][t], b1f[t][0], b1f[t][1]);
                mma16816(c2[0], fb[0][t], b2f[t][0], b2f[t][1]);
                mma16816(c2[1], fb[1][t], b2f[t][0], b2f[t][1]);
            }
            const int cA = 8*j + 2*T;
            const float dAlo = DDT[ g   *DPITCH + cA], dBlo = DDT[ g   *DPITCH + cA+1];
            const float dAhi = DDT[(g+8)*DPITCH + cA], dBhi = DDT[(g+8)*DPITCH + cA+1];
            const float o1A = b1v[cA], o1B = b1v[cA+1];
            const float o2A = b2v[cA], o2B = b2v[cA+1];
#pragma unroll
            for (int m = 0; m < 2; ++m) {
                float z0 = (c1[m][0] + o1A) + dAlo*(c2[m][0] + o2A);
                float z1 = (c1[m][1] + o1B) + dBlo*(c2[m][1] + o2B);
                float z2 = (c1[m][2] + o1A) + dAhi*(c2[m][2] + o2A);
                float z3 = (c1[m][3] + o1B) + dBhi*(c2[m][3] + o2B);
                fz[m][j>>1][2*(j&1) + 0] = pack2(z0, z1);
                fz[m][j>>1][2*(j&1) + 1] = pack2(z2, z3);
            }
        }

        // ---- GEMM3 (z @ folded_ge_w1^T), relu -> h3 frags (reuse fa) ----
#pragma unroll
        for (int j = 0; j < 8; ++j) {
            const __half* wr3 = W3s + (8*j + g)*WPITCH + 2*T;
            uint32_t b3f[4][2];
#pragma unroll
            for (int t = 0; t < 4; ++t) {
                b3f[t][0] = *(const uint32_t*)(wr3 + 16*t);
                b3f[t][1] = *(const uint32_t*)(wr3 + 16*t + 8);
            }
            float c3[2][4] = {{0,0,0,0},{0,0,0,0}};
#pragma unroll
            for (int t = 0; t < 4; ++t) {
                mma16816(c3[0], fz[0][t], b3f[t][0], b3f[t][1]);
                mma16816(c3[1], fz[1][t], b3f[t][0], b3f[t][1]);
            }
            const int cA = 8*j + 2*T;
            const float o3A = b3v[cA], o3B = b3v[cA+1];
#pragma unroll
            for (int m = 0; m < 2; ++m) {
                float h0 = fmaxf(c3[m][0] + o3A, 0.f);
                float h1 = fmaxf(c3[m][1] + o3B, 0.f);
                float h2_ = fmaxf(c3[m][2] + o3A, 0.f);
                float h3_ = fmaxf(c3[m][3] + o3B, 0.f);
                fa[m][j>>1][2*(j&1) + 0] = pack2(h0, h1);
                fa[m][j>>1][2*(j&1) + 1] = pack2(h2_, h3_);
            }
        }

        // ---- GEMM4 (h3 @ ge_w2^T) + bias + store ----
        float* ob = out + (size_t)b * 64 * NNK + pgb0;
#pragma unroll
        for (int j = 0; j < 8; ++j) {
            const __half* wr4 = W4s + (8*j + g)*WPITCH + 2*T;
            uint32_t b4f[4][2];
#pragma unroll
            for (int t = 0; t < 4; ++t) {
                b4f[t][0] = *(const uint32_t*)(wr4 + 16*t);
                b4f[t][1] = *(const uint32_t*)(wr4 + 16*t + 8);
            }
            float c4[2][4] = {{0,0,0,0},{0,0,0,0}};
#pragma unroll
            for (int t = 0; t < 4; ++t) {
                mma16816(c4[0], fa[0][t], b4f[t][0], b4f[t][1]);
                mma16816(c4[1], fa[1][t], b4f[t][0], b4f[t][1]);
            }
            const int cA = 8*j + 2*T;
            const float boA = bov[cA], boB = bov[cA+1];
#pragma unroll
            for (int m = 0; m < 2; ++m) {
                const int rlo = 16*m + g, rhi = rlo + 8;
                ob[(size_t) cA   *NNK + rlo] = c4[m][0] + boA;
                ob[(size_t)(cA+1)*NNK + rlo] = c4[m][1] + boB;
                ob[(size_t) cA   *NNK + rhi] = c4[m][2] + boA;
                ob[(size_t)(cA+1)*NNK + rhi] = c4[m][3] + boB;
            }
        }
    }
}

extern "C" void kernel_launch(void* const* d_in, const int* in_sizes, int n_in,
                              void* d_out, int out_size) {
    (void)in_sizes; (void)n_in; (void)out_size;

    cudaFuncSetAttribute(geo_hmma_kernel,
                         cudaFuncAttributeMaxDynamicSharedMemorySize, SMEM_BYTES);

    geo_hmma_kernel<<<GRID, TPB, SMEM_BYTES>>>(
        (const float*)d_in[0],  (const float*)d_in[1],  (const float*)d_in[2],
        (const float*)d_in[3],  (const float*)d_in[4],  (const float*)d_in[5],
        (const float*)d_in[6],  (const float*)d_in[7],  (const float*)d_in[8],
        (const float*)d_in[9],  (const float*)d_in[10],
        (const float*)d_in[11], (const float*)d_in[12], (const float*)d_in[13],
        (const float*)d_in[14], (const float*)d_in[15], (const float*)d_in[16],
        (const float*)d_in[17], (const float*)d_in[18],
        (const float*)d_in[19], (const float*)d_in[20], (const float*)d_in[21],
        (const float*)d_in[22], (const float*)d_in[23], (const float*)d_in[24],
        (const float*)d_in[25], (const float*)d_in[26],
        (float*)d_out);
}

// round 14
// speedup vs baseline: 15.1841x; 1.0629x over previous
#include <cuda_runtime.h>
#include <cuda_fp16.h>
#include <math.h>
#include <stdint.h>

#define TPB   128
#define GRID  444            // 148 SMs * 3 CTAs
#define NNK   131072         // N*K per (b,c) plane
#define NWT   32768          // total warp tiles (1,048,576 pos / 32)
#define WPITCH 72            // halfs per weight row (conflict-free B-frag loads)
#define DPITCH 68            // floats per ddt row

// ---- smem layout (bytes) ----
#define OFF_W1   0           // cf_w2   f16 [64][WPITCH]
#define OFF_W2   9216        // pl_w2
#define OFF_W3   18432       // folded ge_w1
#define OFF_W4   27648       // ge_w2
#define OFF_W5   36864       // padded folded cf_w1 [64][8] f16 (col6 = bias)
#define OFF_W6   37888       // padded folded pl_w1 [64][8] f16 (col6 = bias)
#define OFF_b1v  38912       // cf_b2 f32
#define OFF_b2v  39168       // pl_b2
#define OFF_b3v  39424       // folded ge bias
#define OFF_bov  39680       // ge_b2
#define OFF_DDT  39936       // d transposed [16][DPITCH] f32
#define SMEM_BYTES (OFF_DDT + 16*DPITCH*4)   // 44288

__device__ __forceinline__ void mma16816(float* c, const uint32_t* a,
                                         uint32_t b0, uint32_t b1) {
    asm volatile(
        "mma.sync.aligned.m16n8k16.row.col.f32.f16.f16.f32 "
        "{%0,%1,%2,%3}, {%4,%5,%6,%7}, {%8,%9}, {%0,%1,%2,%3};"
        : "+f"(c[0]), "+f"(c[1]), "+f"(c[2]), "+f"(c[3])
        : "r"(a[0]), "r"(a[1]), "r"(a[2]), "r"(a[3]), "r"(b0), "r"(b1));
}
__device__ __forceinline__ void mma16808(float* c, uint32_t a0, uint32_t a1,
                                         uint32_t b0) {
    asm volatile(
        "mma.sync.aligned.m16n8k8.row.col.f32.f16.f16.f32 "
        "{%0,%1,%2,%3}, {%4,%5}, {%6}, {%0,%1,%2,%3};"
        : "+f"(c[0]), "+f"(c[1]), "+f"(c[2]), "+f"(c[3])
        : "r"(a0), "r"(a1), "r"(b0));
}
__device__ __forceinline__ uint32_t pack2(float a, float b) {
    __half2 h = __floats2half2_rn(a, b);
    return *reinterpret_cast<uint32_t*>(&h);
}

__global__ void __launch_bounds__(TPB, 3) geo_hmma_kernel(
    const float* __restrict__ nb,    const float* __restrict__ cx,    const float* __restrict__ dmat,
    const float* __restrict__ cf_w1, const float* __restrict__ cf_b1, const float* __restrict__ cf_g,
    const float* __restrict__ cf_be, const float* __restrict__ cf_m,  const float* __restrict__ cf_v,
    const float* __restrict__ cf_w2, const float* __restrict__ cf_b2,
    const float* __restrict__ pl_w1, const float* __restrict__ pl_b1, const float* __restrict__ pl_g,
    const float* __restrict__ pl_be, const float* __restrict__ pl_m,  const float* __restrict__ pl_v,
    const float* __restrict__ pl_w2, const float* __restrict__ pl_b2,
    const float* __restrict__ ge_w1, const float* __restrict__ ge_b1, const float* __restrict__ ge_g,
    const float* __restrict__ ge_be, const float* __restrict__ ge_m,  const float* __restrict__ ge_v,
    const float* __restrict__ ge_w2, const float* __restrict__ ge_b2,
    float* __restrict__ out)
{
    extern __shared__ char smc[];
    __half* W1s = (__half*)(smc + OFF_W1);
    __half* W2s = (__half*)(smc + OFF_W2);
    __half* W3s = (__half*)(smc + OFF_W3);
    __half* W4s = (__half*)(smc + OFF_W4);
    __half* W5s = (__half*)(smc + OFF_W5);
    __half* W6s = (__half*)(smc + OFF_W6);
    float*  b1v = (float*)(smc + OFF_b1v);
    float*  b2v = (float*)(smc + OFF_b2v);
    float*  b3v = (float*)(smc + OFF_b3v);
    float*  bov = (float*)(smc + OFF_bov);
    float*  DDT = (float*)(smc + OFF_DDT);

    const int tid = threadIdx.x;

    // ---- prologue: fold BN, convert weights to f16 ----
    for (int idx = tid; idx < 4096; idx += TPB) {
        int n_ = idx >> 6, k_ = idx & 63;
        float s3 = ge_g[n_] * rsqrtf(ge_v[n_] + 1e-5f);
        W1s[n_*WPITCH + k_] = __float2half_rn(cf_w2[idx]);
        W2s[n_*WPITCH + k_] = __float2half_rn(pl_w2[idx]);
        W3s[n_*WPITCH + k_] = __float2half_rn(s3 * ge_w1[idx]);
        W4s[n_*WPITCH + k_] = __float2half_rn(ge_w2[idx]);
    }
    for (int idx = tid; idx < 1024; idx += TPB) {
        int c_ = idx >> 4, k_ = idx & 15;
        DDT[k_*DPITCH + c_] = dmat[idx];
    }
    if (tid < 64) {
        const int c = tid;
        float s = cf_g[c] * rsqrtf(cf_v[c] + 1e-5f);
        W5s[c*8+0] = __float2half_rn(s * cf_w1[c*4+0]);
        W5s[c*8+1] = __float2half_rn(s * cf_w1[c*4+1]);
        W5s[c*8+2] = __float2half_rn(s * cf_w1[c*4+2]);
        W5s[c*8+3] = __float2half_rn(s * cf_w1[c*4+3]);
        W5s[c*8+4] = __float2half_rn(0.f);
        W5s[c*8+5] = __float2half_rn(0.f);
        W5s[c*8+6] = __float2half_rn(s * (cf_b1[c] - cf_m[c]) + cf_be[c]);
        W5s[c*8+7] = __float2half_rn(0.f);

        float s2 = pl_g[c] * rsqrtf(pl_v[c] + 1e-5f);
        W6s[c*8+0] = __float2half_rn(0.f);
        W6s[c*8+1] = __float2half_rn(0.f);
        W6s[c*8+2] = __float2half_rn(0.f);
        W6s[c*8+3] = __float2half_rn(0.f);
        W6s[c*8+4] = __float2half_rn(s2 * pl_w1[c*2+0]);   // ca weight
        W6s[c*8+5] = __float2half_rn(s2 * pl_w1[c*2+1]);   // ce weight
        W6s[c*8+6] = __float2half_rn(s2 * (pl_b1[c] - pl_m[c]) + pl_be[c]);
        W6s[c*8+7] = __float2half_rn(0.f);

        float s3 = ge_g[c] * rsqrtf(ge_v[c] + 1e-5f);
        b3v[c] = s3 * (ge_b1[c] - ge_m[c]) + ge_be[c];
        b1v[c] = cf_b2[c];
        b2v[c] = pl_b2[c];
        bov[c] = ge_b2[c];
    }
    __syncthreads();

    const int lane = tid & 31;
    const int g    = lane >> 2;        // 0..7
    const int T    = lane & 3;         // 0..3
    const int warp_global = blockIdx.x * (TPB/32) + (tid >> 5);
    const int stride = GRID * (TPB/32);

    const uint32_t PCONST = pack2(1.f, 0.f);   // X cols 6,7

    for (int wt = warp_global; wt < NWT; wt += stride) {
        const int b    = wt >> 12;               // 4096 tiles per batch
        const int pgb0 = (wt & 4095) << 5;       // base position in batch
        const int pgb  = pgb0 + lane;
        const int n    = pgb >> 4;

        // ---- geometry for own position (lane = row) ----
        const float* nbb = nb + (size_t)b * 3 * NNK;
        const float* cxb = cx + (size_t)b * 3 * 8192;
        const float dx = nbb[0*NNK + pgb] - cxb[0*8192 + n];
        const float dy = nbb[1*NNK + pgb] - cxb[1*8192 + n];
        const float dz = nbb[2*NNK + pgb] - cxb[2*8192 + n];
        const float r   = sqrtf(dx*dx + dy*dy + dz*dz);
        const float rxy = sqrtf(dx*dx + dy*dy);
        const float ce  = (r   > 0.f) ? (rxy / r)  : 0.f;
        const float ca  = (rxy > 0.f) ? (dy / rxy) : 0.f;

        // ---- build X A-fragments: X[32 pos][8] = [dx,dy,dz,r,ca,ce,1,0] ----
        const uint32_t p0 = pack2(dx, dy);
        const uint32_t p1 = pack2(dz, r);
        const uint32_t p2 = pack2(ca, ce);
        uint32_t xa[2][2];   // [mtile][reg]
#pragma unroll
        for (int rr = 0; rr < 4; ++rr) {
            const int src = g + 8*rr;
            uint32_t q0 = __shfl_sync(0xffffffffu, p0, src);
            uint32_t q1 = __shfl_sync(0xffffffffu, p1, src);
            uint32_t q2 = __shfl_sync(0xffffffffu, p2, src);
            uint32_t v  = (T == 0) ? q0 : (T == 1) ? q1 : (T == 2) ? q2 : PCONST;
            xa[rr>>1][rr&1] = v;
        }

        // ---- stage 0: h1 = relu(X@W5^T), h2 = relu(X@W6^T) via k8 MMA ----
        uint32_t fa[2][4][4];   // h1 frags  [m][ktile][reg]
        uint32_t fb[2][4][4];   // h2 frags
#pragma unroll
        for (int j = 0; j < 8; ++j) {
            const uint32_t b5 = *(const uint32_t*)(W5s + (8*j + g)*8 + 2*T);
            const uint32_t b6 = *(const uint32_t*)(W6s + (8*j + g)*8 + 2*T);
            float c5[2][4] = {{0,0,0,0},{0,0,0,0}};
            float c6[2][4] = {{0,0,0,0},{0,0,0,0}};
#pragma unroll
            for (int m = 0; m < 2; ++m) {
                mma16808(c5[m], xa[m][0], xa[m][1], b5);
                mma16808(c6[m], xa[m][0], xa[m][1], b6);
            }
#pragma unroll
            for (int m = 0; m < 2; ++m) {
                fa[m][j>>1][2*(j&1)+0] = pack2(fmaxf(c5[m][0],0.f), fmaxf(c5[m][1],0.f));
                fa[m][j>>1][2*(j&1)+1] = pack2(fmaxf(c5[m][2],0.f), fmaxf(c5[m][3],0.f));
                fb[m][j>>1][2*(j&1)+0] = pack2(fmaxf(c6[m][0],0.f), fmaxf(c6[m][1],0.f));
                fb[m][j>>1][2*(j&1)+1] = pack2(fmaxf(c6[m][2],0.f), fmaxf(c6[m][3],0.f));
            }
        }

        // ---- GEMM1 (h1 @ cf_w2^T) + GEMM2 (h2 @ pl_w2^T) + z epilogue ----
        uint32_t fz[2][4][4];   // z frags
#pragma unroll
        for (int j = 0; j < 8; ++j) {
            const __half* wr1 = W1s + (8*j + g)*WPITCH + 2*T;
            const __half* wr2 = W2s + (8*j + g)*WPITCH + 2*T;
            uint32_t b1f[4][2], b2f[4][2];
#pragma unroll
            for (int t = 0; t < 4; ++t) {
                b1f[t][0] = *(const uint32_t*)(wr1 + 16*t);
                b1f[t][1] = *(const uint32_t*)(wr1 + 16*t + 8);
                b2f[t][0] = *(const uint32_t*)(wr2 + 16*t);
                b2f[t][1] = *(const uint32_t*)(wr2 + 16*t + 8);
            }
            float c1[2][4] = {{0,0,0,0},{0,0,0,0}};
            float c2[2][4] = {{0,0,0,0},{0,0,0,0}};
#pragma unroll
            for (int t = 0; t < 4; ++t) {
                mma16816(c1[0], fa[0][t], b1f[t][0], b1f[t][1]);
                mma16816(c1[1], fa[1][t], b1f[t][0], b1f[t][1]);
                mma16816(c2[0], fb[0][t], b2f[t][0], b2f[t][1]);
                mma16816(c2[1], fb[1][t], b2f[t][0], b2f[t][1]);
            }
            const int cA = 8*j + 2*T;
            const float dAlo = DDT[ g   *DPITCH + cA], dBlo = DDT[ g   *DPITCH + cA+1];
            const float dAhi = DDT[(g+8)*DPITCH + cA], dBhi = DDT[(g+8)*DPITCH + cA+1];
            const float o1A = b1v[cA], o1B = b1v[cA+1];
            const float o2A = b2v[cA], o2B = b2v[cA+1];
#pragma unroll
            for (int m = 0; m < 2; ++m) {
                float z0 = (c1[m][0] + o1A) + dAlo*(c2[m][0] + o2A);
                float z1 = (c1[m][1] + o1B) + dBlo*(c2[m][1] + o2B);
                float z2 = (c1[m][2] + o1A) + dAhi*(c2[m][2] + o2A);
                float z3 = (c1[m][3] + o1B) + dBhi*(c2[m][3] + o2B);
                fz[m][j>>1][2*(j&1) + 0] = pack2(z0, z1);
                fz[m][j>>1][2*(j&1) + 1] = pack2(z2, z3);
            }
        }

        // ---- GEMM3 (z @ folded_ge_w1^T), relu -> h3 frags (reuse fa) ----
#pragma unroll
        for (int j = 0; j < 8; ++j) {
            const __half* wr3 = W3s + (8*j + g)*WPITCH + 2*T;
            uint32_t b3f[4][2];
#pragma unroll
            for (int t = 0; t < 4; ++t) {
                b3f[t][0] = *(const uint32_t*)(wr3 + 16*t);
                b3f[t][1] = *(const uint32_t*)(wr3 + 16*t + 8);
            }
            float c3[2][4] = {{0,0,0,0},{0,0,0,0}};
#pragma unroll
            for (int t = 0; t < 4; ++t) {
                mma16816(c3[0], fz[0][t], b3f[t][0], b3f[t][1]);
                mma16816(c3[1], fz[1][t], b3f[t][0], b3f[t][1]);
            }
            const int cA = 8*j + 2*T;
            const float o3A = b3v[cA], o3B = b3v[cA+1];
#pragma unroll
            for (int m = 0; m < 2; ++m) {
                float h0 = fmaxf(c3[m][0] + o3A, 0.f);
                float h1 = fmaxf(c3[m][1] + o3B, 0.f);
                float h2_ = fmaxf(c3[m][2] + o3A, 0.f);
                float h3_ = fmaxf(c3[m][3] + o3B, 0.f);
                fa[m][j>>1][2*(j&1) + 0] = pack2(h0, h1);
                fa[m][j>>1][2*(j&1) + 1] = pack2(h2_, h3_);
            }
        }

        // ---- GEMM4 (h3 @ ge_w2^T) + bias + store ----
        float* ob = out + (size_t)b * 64 * NNK + pgb0;
#pragma unroll
        for (int j = 0; j < 8; ++j) {
            const __half* wr4 = W4s + (8*j + g)*WPITCH + 2*T;
            uint32_t b4f[4][2];
#pragma unroll
            for (int t = 0; t < 4; ++t) {
                b4f[t][0] = *(const uint32_t*)(wr4 + 16*t);
                b4f[t][1] = *(const uint32_t*)(wr4 + 16*t + 8);
            }
            float c4[2][4] = {{0,0,0,0},{0,0,0,0}};
#pragma unroll
            for (int t = 0; t < 4; ++t) {
                mma16816(c4[0], fa[0][t], b4f[t][0], b4f[t][1]);
                mma16816(c4[1], fa[1][t], b4f[t][0], b4f[t][1]);
            }
            const int cA = 8*j + 2*T;
            const float boA = bov[cA], boB = bov[cA+1];
#pragma unroll
            for (int m = 0; m < 2; ++m) {
                const int rlo = 16*m + g, rhi = rlo + 8;
                ob[(size_t) cA   *NNK + rlo] = c4[m][0] + boA;
                ob[(size_t)(cA+1)*NNK + rlo] = c4[m][1] + boB;
                ob[(size_t) cA   *NNK + rhi] = c4[m][2] + boA;
                ob[(size_t)(cA+1)*NNK + rhi] = c4[m][3] + boB;
            }
        }
    }
}

extern "C" void kernel_launch(void* const* d_in, const int* in_sizes, int n_in,
                              void* d_out, int out_size) {
    (void)in_sizes; (void)n_in; (void)out_size;

    cudaFuncSetAttribute(geo_hmma_kernel,
                         cudaFuncAttributeMaxDynamicSharedMemorySize, SMEM_BYTES);

    geo_hmma_kernel<<<GRID, TPB, SMEM_BYTES>>>(
        (const float*)d_in[0],  (const float*)d_in[1],  (const float*)d_in[2],
        (const float*)d_in[3],  (const float*)d_in[4],  (const float*)d_in[5],
        (const float*)d_in[6],  (const float*)d_in[7],  (const float*)d_in[8],
        (const float*)d_in[9],  (const float*)d_in[10],
        (const float*)d_in[11], (const float*)d_in[12], (const float*)d_in[13],
        (const float*)d_in[14], (const float*)d_in[15], (const float*)d_in[16],
        (const float*)d_in[17], (const float*)d_in[18],
        (const float*)d_in[19], (const float*)d_in[20], (const float*)d_in[21],
        (const float*)d_in[22], (const float*)d_in[23], (const float*)d_in[24],
        (const float*)d_in[25], (const float*)d_in[26],
        (float*)d_out);
}

// round 15
// speedup vs baseline: 15.4483x; 1.0174x over previous
#include <cuda_runtime.h>
#include <cuda_fp16.h>
#include <math.h>
#include <stdint.h>

#define TPB   128
#define GRID  444            // 148 SMs * 3 CTAs
#define NNK   131072         // N*K per (b,c) plane
#define NWT   32768          // total warp tiles (1,048,576 pos / 32)
#define DPITCH 72            // floats per ddt row (32B phase spread, conflict-free)

// ---- smem layout (bytes) ----
// packed weight quads: row pitch 160B, 64 rows = 10240B each
#define OFF_P1   0           // cf_w2
#define OFF_P2   10240       // pl_w2
#define OFF_P3   20480       // folded ge_w1
#define OFF_P4   30720       // ge_w2
#define OFF_P56  40960       // stage0: [W5 pair | W6 pair] per (row,T)
#define OFF_b1v  51200       // cf_b2 f32
#define OFF_b2v  51456       // pl_b2
#define OFF_b3v  51712       // folded ge bias
#define OFF_bov  51968       // ge_b2
#define OFF_DDT  52224       // d transposed [16][DPITCH] f32
#define SMEM_BYTES (OFF_DDT + 16*DPITCH*4)   // 56832 -> 3 CTAs/SM

__device__ __forceinline__ void mma16816(float* c, const uint32_t* a,
                                         uint32_t b0, uint32_t b1) {
    asm volatile(
        "mma.sync.aligned.m16n8k16.row.col.f32.f16.f16.f32 "
        "{%0,%1,%2,%3}, {%4,%5,%6,%7}, {%8,%9}, {%0,%1,%2,%3};"
        : "+f"(c[0]), "+f"(c[1]), "+f"(c[2]), "+f"(c[3])
        : "r"(a[0]), "r"(a[1]), "r"(a[2]), "r"(a[3]), "r"(b0), "r"(b1));
}
__device__ __forceinline__ void mma16808(float* c, uint32_t a0, uint32_t a1,
                                         uint32_t b0) {
    asm volatile(
        "mma.sync.aligned.m16n8k8.row.col.f32.f16.f16.f32 "
        "{%0,%1,%2,%3}, {%4,%5}, {%6}, {%0,%1,%2,%3};"
        : "+f"(c[0]), "+f"(c[1]), "+f"(c[2]), "+f"(c[3])
        : "r"(a0), "r"(a1), "r"(b0));
}
__device__ __forceinline__ uint32_t pack2(float a, float b) {
    __half2 h = __floats2half2_rn(a, b);
    return *reinterpret_cast<uint32_t*>(&h);
}

__global__ void __launch_bounds__(TPB, 3) geo_hmma_kernel(
    const float* __restrict__ nb,    const float* __restrict__ cx,    const float* __restrict__ dmat,
    const float* __restrict__ cf_w1, const float* __restrict__ cf_b1, const float* __restrict__ cf_g,
    const float* __restrict__ cf_be, const float* __restrict__ cf_m,  const float* __restrict__ cf_v,
    const float* __restrict__ cf_w2, const float* __restrict__ cf_b2,
    const float* __restrict__ pl_w1, const float* __restrict__ pl_b1, const float* __restrict__ pl_g,
    const float* __restrict__ pl_be, const float* __restrict__ pl_m,  const float* __restrict__ pl_v,
    const float* __restrict__ pl_w2, const float* __restrict__ pl_b2,
    const float* __restrict__ ge_w1, const float* __restrict__ ge_b1, const float* __restrict__ ge_g,
    const float* __restrict__ ge_be, const float* __restrict__ ge_m,  const float* __restrict__ ge_v,
    const float* __restrict__ ge_w2, const float* __restrict__ ge_b2,
    float* __restrict__ out)
{
    extern __shared__ char smc[];
    __half* P1  = (__half*)(smc + OFF_P1);
    __half* P2  = (__half*)(smc + OFF_P2);
    __half* P3  = (__half*)(smc + OFF_P3);
    __half* P4  = (__half*)(smc + OFF_P4);
    __half* P56 = (__half*)(smc + OFF_P56);
    float*  b1v = (float*)(smc + OFF_b1v);
    float*  b2v = (float*)(smc + OFF_b2v);
    float*  b3v = (float*)(smc + OFF_b3v);
    float*  bov = (float*)(smc + OFF_bov);
    float*  DDT = (float*)(smc + OFF_DDT);

    const int tid = threadIdx.x;

    // ---- prologue: fold BN, convert to f16, pack B-fragment quads ----
    // quad layout (halfs): doff = row*80 + t*16 + T*4 + slot
    //   slot 0,1 = k 16t+2T, 16t+2T+1  (b0) ; slot 2,3 = k 16t+2T+8, +9 (b1)
    for (int idx = tid; idx < 4096; idx += TPB) {
        int n_ = idx >> 6, k_ = idx & 63;
        int t  = k_ >> 4, r_ = k_ & 15;
        int hi = r_ >> 3;
        int Tq = (r_ & 7) >> 1;
        int slot = hi * 2 + (r_ & 1);
        int doff = n_ * 80 + t * 16 + Tq * 4 + slot;
        float s3 = ge_g[n_] * rsqrtf(ge_v[n_] + 1e-5f);
        P1[doff] = __float2half_rn(cf_w2[idx]);
        P2[doff] = __float2half_rn(pl_w2[idx]);
        P3[doff] = __float2half_rn(s3 * ge_w1[idx]);
        P4[doff] = __float2half_rn(ge_w2[idx]);
    }
    for (int idx = tid; idx < 1024; idx += TPB) {
        int c_ = idx >> 4, k_ = idx & 15;
        DDT[k_ * DPITCH + c_] = dmat[idx];
    }
    if (tid < 64) {
        const int c = tid;
        float s  = cf_g[c] * rsqrtf(cf_v[c] + 1e-5f);
        float s2 = pl_g[c] * rsqrtf(pl_v[c] + 1e-5f);
        float w5[8], w6[8];
#pragma unroll
        for (int i = 0; i < 8; ++i) { w5[i] = 0.f; w6[i] = 0.f; }
        w5[0] = s * cf_w1[c*4+0];  w5[1] = s * cf_w1[c*4+1];
        w5[2] = s * cf_w1[c*4+2];  w5[3] = s * cf_w1[c*4+3];
        w5[6] = s * (cf_b1[c] - cf_m[c]) + cf_be[c];
        w6[4] = s2 * pl_w1[c*2+0]; w6[5] = s2 * pl_w1[c*2+1];
        w6[6] = s2 * (pl_b1[c] - pl_m[c]) + pl_be[c];
#pragma unroll
        for (int T = 0; T < 4; ++T) {
            int base = c * 80 + T * 4;
            P56[base+0] = __float2half_rn(w5[2*T]);
            P56[base+1] = __float2half_rn(w5[2*T+1]);
            P56[base+2] = __float2half_rn(w6[2*T]);
            P56[base+3] = __float2half_rn(w6[2*T+1]);
        }
        float s3 = ge_g[c] * rsqrtf(ge_v[c] + 1e-5f);
        b3v[c] = s3 * (ge_b1[c] - ge_m[c]) + ge_be[c];
        b1v[c] = cf_b2[c];
        b2v[c] = pl_b2[c];
        bov[c] = ge_b2[c];
    }
    __syncthreads();

    const int lane = tid & 31;
    const int g    = lane >> 2;        // 0..7
    const int T    = lane & 3;         // 0..3
    const int warp_global = blockIdx.x * (TPB/32) + (tid >> 5);
    const int stride = GRID * (TPB/32);

    const uint32_t PCONST = pack2(1.f, 0.f);   // X cols 6,7

    // ---- geometry prefetch for first tile ----
    float pnx, pny, pnz, pcx, pcy, pcz;
    {
        const int wt0 = warp_global;
        const int b   = wt0 >> 12;
        const int pgb = ((wt0 & 4095) << 5) + lane;
        const int n   = pgb >> 4;
        const float* nbb = nb + (size_t)b * 3 * NNK;
        const float* cxb = cx + (size_t)b * 3 * 8192;
        pnx = nbb[0*NNK + pgb];  pny = nbb[1*NNK + pgb];  pnz = nbb[2*NNK + pgb];
        pcx = cxb[0*8192 + n];   pcy = cxb[1*8192 + n];   pcz = cxb[2*8192 + n];
    }

    for (int wt = warp_global; wt < NWT; wt += stride) {
        const int b    = wt >> 12;               // 4096 tiles per batch
        const int pgb0 = (wt & 4095) << 5;       // base position in batch

        // ---- consume prefetched geometry ----
        const float dx = pnx - pcx;
        const float dy = pny - pcy;
        const float dz = pnz - pcz;
        const float r   = sqrtf(dx*dx + dy*dy + dz*dz);
        const float rxy = sqrtf(dx*dx + dy*dy);
        const float ce  = (r   > 0.f) ? (rxy / r)  : 0.f;
        const float ca  = (rxy > 0.f) ? (dy / rxy) : 0.f;

        // ---- issue next tile's loads; latency hides under the GEMM chain ----
        const int nwt = wt + stride;
        if (nwt < NWT) {
            const int nb_ = nwt >> 12;
            const int pgb = ((nwt & 4095) << 5) + lane;
            const int n   = pgb >> 4;
            const float* nbb = nb + (size_t)nb_ * 3 * NNK;
            const float* cxb = cx + (size_t)nb_ * 3 * 8192;
            pnx = nbb[0*NNK + pgb];  pny = nbb[1*NNK + pgb];  pnz = nbb[2*NNK + pgb];
            pcx = cxb[0*8192 + n];   pcy = cxb[1*8192 + n];   pcz = cxb[2*8192 + n];
        }

        // ---- build X A-fragments: X[32 pos][8] = [dx,dy,dz,r,ca,ce,1,0] ----
        const uint32_t p0 = pack2(dx, dy);
        const uint32_t p1 = pack2(dz, r);
        const uint32_t p2 = pack2(ca, ce);
        uint32_t xa[2][2];
#pragma unroll
        for (int rr = 0; rr < 4; ++rr) {
            const int src = g + 8*rr;
            uint32_t q0 = __shfl_sync(0xffffffffu, p0, src);
            uint32_t q1 = __shfl_sync(0xffffffffu, p1, src);
            uint32_t q2 = __shfl_sync(0xffffffffu, p2, src);
            uint32_t v  = (T == 0) ? q0 : (T == 1) ? q1 : (T == 2) ? q2 : PCONST;
            xa[rr>>1][rr&1] = v;
        }

        // ---- stage 0: h1 = relu(X@W5^T), h2 = relu(X@W6^T) via k8 MMA ----
        uint32_t fa[2][4][4];
        uint32_t fb[2][4][4];
#pragma unroll
        for (int j = 0; j < 8; ++j) {
            const uint2 v56 = *(const uint2*)(smc + OFF_P56 + (8*j + g)*160 + T*8);
            float c5[2][4] = {{0,0,0,0},{0,0,0,0}};
            float c6[2][4] = {{0,0,0,0},{0,0,0,0}};
#pragma unroll
            for (int m = 0; m < 2; ++m) {
                mma16808(c5[m], xa[m][0], xa[m][1], v56.x);
                mma16808(c6[m], xa[m][0], xa[m][1], v56.y);
            }
#pragma unroll
            for (int m = 0; m < 2; ++m) {
                fa[m][j>>1][2*(j&1)+0] = pack2(fmaxf(c5[m][0],0.f), fmaxf(c5[m][1],0.f));
                fa[m][j>>1][2*(j&1)+1] = pack2(fmaxf(c5[m][2],0.f), fmaxf(c5[m][3],0.f));
                fb[m][j>>1][2*(j&1)+0] = pack2(fmaxf(c6[m][0],0.f), fmaxf(c6[m][1],0.f));
                fb[m][j>>1][2*(j&1)+1] = pack2(fmaxf(c6[m][2],0.f), fmaxf(c6[m][3],0.f));
            }
        }

        // ---- GEMM1 (h1 @ cf_w2^T) + GEMM2 (h2 @ pl_w2^T) + z epilogue ----
        uint32_t fz[2][4][4];
#pragma unroll
        for (int j = 0; j < 8; ++j) {
            const char* q1 = smc + OFF_P1 + (8*j + g)*160 + T*8;
            const char* q2 = smc + OFF_P2 + (8*j + g)*160 + T*8;
            float c1[2][4] = {{0,0,0,0},{0,0,0,0}};
            float c2[2][4] = {{0,0,0,0},{0,0,0,0}};
#pragma unroll
            for (int t = 0; t < 4; ++t) {
                const uint2 v1 = *(const uint2*)(q1 + t*32);
                const uint2 v2 = *(const uint2*)(q2 + t*32);
                mma16816(c1[0], fa[0][t], v1.x, v1.y);
                mma16816(c1[1], fa[1][t], v1.x, v1.y);
                mma16816(c2[0], fb[0][t], v2.x, v2.y);
                mma16816(c2[1], fb[1][t], v2.x, v2.y);
            }
            const int cA = 8*j + 2*T;
            const float2 dlo = *(const float2*)(DDT +  g   *DPITCH + cA);
            const float2 dhi = *(const float2*)(DDT + (g+8)*DPITCH + cA);
            const float2 o1  = *(const float2*)(b1v + cA);
            const float2 o2  = *(const float2*)(b2v + cA);
#pragma unroll
            for (int m = 0; m < 2; ++m) {
                float z0 = (c1[m][0] + o1.x) + dlo.x*(c2[m][0] + o2.x);
                float z1 = (c1[m][1] + o1.y) + dlo.y*(c2[m][1] + o2.y);
                float z2 = (c1[m][2] + o1.x) + dhi.x*(c2[m][2] + o2.x);
                float z3 = (c1[m][3] + o1.y) + dhi.y*(c2[m][3] + o2.y);
                fz[m][j>>1][2*(j&1) + 0] = pack2(z0, z1);
                fz[m][j>>1][2*(j&1) + 1] = pack2(z2, z3);
            }
        }

        // ---- GEMM3 (z @ folded_ge_w1^T), relu -> h3 frags (reuse fa) ----
#pragma unroll
        for (int j = 0; j < 8; ++j) {
            const char* q3 = smc + OFF_P3 + (8*j + g)*160 + T*8;
            float c3[2][4] = {{0,0,0,0},{0,0,0,0}};
#pragma unroll
            for (int t = 0; t < 4; ++t) {
                const uint2 v3 = *(const uint2*)(q3 + t*32);
                mma16816(c3[0], fz[0][t], v3.x, v3.y);
                mma16816(c3[1], fz[1][t], v3.x, v3.y);
            }
            const int cA = 8*j + 2*T;
            const float2 o3 = *(const float2*)(b3v + cA);
#pragma unroll
            for (int m = 0; m < 2; ++m) {
                float h0  = fmaxf(c3[m][0] + o3.x, 0.f);
                float h1  = fmaxf(c3[m][1] + o3.y, 0.f);
                float h2_ = fmaxf(c3[m][2] + o3.x, 0.f);
                float h3_ = fmaxf(c3[m][3] + o3.y, 0.f);
                fa[m][j>>1][2*(j&1) + 0] = pack2(h0, h1);
                fa[m][j>>1][2*(j&1) + 1] = pack2(h2_, h3_);
            }
        }

        // ---- GEMM4 (h3 @ ge_w2^T) + bias + store ----
        float* ob = out + (size_t)b * 64 * NNK + pgb0;
#pragma unroll
        for (int j = 0; j < 8; ++j) {
            const char* q4 = smc + OFF_P4 + (8*j + g)*160 + T*8;
            float c4[2][4] = {{0,0,0,0},{0,0,0,0}};
#pragma unroll
            for (int t = 0; t < 4; ++t) {
                const uint2 v4 = *(const uint2*)(q4 + t*32);
                mma16816(c4[0], fa[0][t], v4.x, v4.y);
                mma16816(c4[1], fa[1][t], v4.x, v4.y);
            }
            const int cA = 8*j + 2*T;
            const float2 o4 = *(const float2*)(bov + cA);
#pragma unroll
            for (int m = 0; m < 2; ++m) {
                const int rlo = 16*m + g, rhi = rlo + 8;
                ob[(size_t) cA   *NNK + rlo] = c4[m][0] + o4.x;
                ob[(size_t)(cA+1)*NNK + rlo] = c4[m][1] + o4.y;
                ob[(size_t) cA   *NNK + rhi] = c4[m][2] + o4.x;
                ob[(size_t)(cA+1)*NNK + rhi] = c4[m][3] + o4.y;
            }
        }
    }
}

extern "C" void kernel_launch(void* const* d_in, const int* in_sizes, int n_in,
                              void* d_out, int out_size) {
    (void)in_sizes; (void)n_in; (void)out_size;

    cudaFuncSetAttribute(geo_hmma_kernel,
                         cudaFuncAttributeMaxDynamicSharedMemorySize, SMEM_BYTES);

    geo_hmma_kernel<<<GRID, TPB, SMEM_BYTES>>>(
        (const float*)d_in[0],  (const float*)d_in[1],  (const float*)d_in[2],
        (const float*)d_in[3],  (const float*)d_in[4],  (const float*)d_in[5],
        (const float*)d_in[6],  (const float*)d_in[7],  (const float*)d_in[8],
        (const float*)d_in[9],  (const float*)d_in[10],
        (const float*)d_in[11], (const float*)d_in[12], (const float*)d_in[13],
        (const float*)d_in[14], (const float*)d_in[15], (const float*)d_in[16],
        (const float*)d_in[17], (const float*)d_in[18],
        (const float*)d_in[19], (const float*)d_in[20], (const float*)d_in[21],
        (const float*)d_in[22], (const float*)d_in[23], (const float*)d_in[24],
        (const float*)d_in[25], (const float*)d_in[26],
        (float*)d_out);
}